// round 1
// baseline (speedup 1.0000x reference)
#include <cuda_runtime.h>
#include <math.h>

#define B_  8
#define C_  256
#define H_  64
#define W_  64
#define HW  (H_*W_)
#define PLANE ((size_t)C_*HW)

// ------------------------- scratch (static device memory) -------------------
__device__ float g_fe [B_*C_*HW];
__device__ float g_agg[B_*C_*HW];
__device__ float g_enh[B_*C_*HW];
__device__ float g_W1 [C_*C_];
__device__ float g_b1 [C_];
__device__ float g_W2 [C_*2*C_];
__device__ float g_b2 [C_];
__device__ float g_pooled[B_*2*C_];
__device__ float g_wts[B_*C_];

// ------------------------- BN folding ---------------------------------------
__global__ void fold_bn_kernel(const float* __restrict__ W, const float* __restrict__ bconv,
                               const float* __restrict__ gamma, const float* __restrict__ beta,
                               const float* __restrict__ mean, const float* __restrict__ var,
                               float* __restrict__ Wo, float* __restrict__ bo, int Kin)
{
    int o = blockIdx.x;
    float inv = gamma[o] / sqrtf(var[o] + 1e-5f);
    for (int i = threadIdx.x; i < Kin; i += blockDim.x)
        Wo[o * Kin + i] = W[o * Kin + i] * inv;
    if (threadIdx.x == 0)
        bo[o] = bconv[o] * inv + beta[o] - mean[o] * inv;
}

// ------------------------- SGEMM: out[b] = relu(A @ X[b] + bias) -------------
// A: [256 x K] row-major (BN-folded weights).
// X rows 0..255 come from X0 (x), rows 256..K-1 from X1 (agg).
// out: (B,256,HW).  BM=BN=128, BK=16, 8x8 per-thread microtile, 256 threads.
__global__ __launch_bounds__(256)
void gemm_bias_relu_kernel(const float* __restrict__ A,
                           const float* __restrict__ X0,
                           const float* __restrict__ X1,
                           const float* __restrict__ bias,
                           float* __restrict__ out, int K)
{
    __shared__ float As[16][128];
    __shared__ float Bs[16][128];

    const int b   = blockIdx.z;
    const int p0  = blockIdx.x * 128;   // pixel (HW) offset
    const int m0  = blockIdx.y * 128;   // output-channel offset
    const int tid = threadIdx.x;
    const int tx  = tid & 15;           // 0..15 -> N
    const int ty  = tid >> 4;           // 0..15 -> M

    float acc[8][8];
#pragma unroll
    for (int i = 0; i < 8; i++)
#pragma unroll
        for (int j = 0; j < 8; j++) acc[i][j] = 0.f;

    const float* xb0 = X0 + (size_t)b * PLANE;
    const float* xb1 = X1 ? (X1 + (size_t)b * PLANE) : nullptr;

    for (int k0 = 0; k0 < K; k0 += 16) {
        // load A tile 128x16 (2 float4 per thread), store transposed
#pragma unroll
        for (int l = 0; l < 2; l++) {
            int idx = tid + l * 256;         // 0..511
            int r   = idx >> 2;              // 0..127
            int c4  = (idx & 3) * 4;         // 0,4,8,12
            float4 v = *(const float4*)(A + (size_t)(m0 + r) * K + k0 + c4);
            As[c4 + 0][r] = v.x; As[c4 + 1][r] = v.y;
            As[c4 + 2][r] = v.z; As[c4 + 3][r] = v.w;
        }
        // load X tile 16x128 (2 float4 per thread)
#pragma unroll
        for (int l = 0; l < 2; l++) {
            int idx = tid + l * 256;
            int r   = idx >> 5;              // 0..15
            int c   = (idx & 31) * 4;        // 0..124
            int ci  = k0 + r;
            const float* src = (ci < C_) ? (xb0 + (size_t)ci * HW)
                                         : (xb1 + (size_t)(ci - C_) * HW);
            *(float4*)&Bs[r][c] = *(const float4*)(src + p0 + c);
        }
        __syncthreads();

#pragma unroll
        for (int kk = 0; kk < 16; kk++) {
            float af[8], bf[8];
#pragma unroll
            for (int i = 0; i < 8; i++) af[i] = As[kk][ty * 8 + i];
#pragma unroll
            for (int j = 0; j < 8; j++) bf[j] = Bs[kk][tx * 8 + j];
#pragma unroll
            for (int i = 0; i < 8; i++)
#pragma unroll
                for (int j = 0; j < 8; j++) acc[i][j] += af[i] * bf[j];
        }
        __syncthreads();
    }

    // epilogue: bias + relu
#pragma unroll
    for (int i = 0; i < 8; i++) {
        int row = m0 + ty * 8 + i;
        float bs = bias[row];
        float* dst = out + (size_t)b * PLANE + (size_t)row * HW + p0 + tx * 8;
#pragma unroll
        for (int j = 0; j < 8; j += 4) {
            float4 v;
            v.x = fmaxf(acc[i][j + 0] + bs, 0.f);
            v.y = fmaxf(acc[i][j + 1] + bs, 0.f);
            v.z = fmaxf(acc[i][j + 2] + bs, 0.f);
            v.w = fmaxf(acc[i][j + 3] + bs, 0.f);
            *(float4*)(dst + j) = v;
        }
    }
}

// ------------- fused cosine similarity + softmax + aggregation --------------
// block = (batch, 8-row tile), 512 threads (8 rows x 64 cols)
__global__ __launch_bounds__(512)
void simagg_kernel(const float* __restrict__ fe, const float* __restrict__ x,
                   float* __restrict__ agg)
{
    const int b  = blockIdx.y;
    const int h0 = blockIdx.x * 8;
    const int tid = threadIdx.x;
    const int lr = tid >> 6;      // 0..7 local row
    const int w  = tid & 63;      // 0..63

    __shared__ float tile[10][66];

    float sim[9], np[9];
#pragma unroll
    for (int k = 0; k < 9; k++) { sim[k] = 0.f; np[k] = 0.f; }

    // pass 1: accumulate dot products and squared norms over channels
    for (int c = 0; c < C_; c++) {
        const float* src = fe + ((size_t)b * C_ + c) * HW;
        for (int idx = tid; idx < 660; idx += 512) {
            int r  = idx / 66, cc = idx % 66;
            int gh = h0 - 1 + r, gw = cc - 1;
            float v = 0.f;
            if ((unsigned)gh < (unsigned)H_ && (unsigned)gw < (unsigned)W_)
                v = src[gh * W_ + gw];
            tile[r][cc] = v;
        }
        __syncthreads();
        float cv = tile[lr + 1][w + 1];
#pragma unroll
        for (int i = 0; i < 3; i++)
#pragma unroll
            for (int j = 0; j < 3; j++) {
                float v = tile[lr + i][w + j];
                sim[i * 3 + j] += cv * v;
                np[i * 3 + j]  += v * v;
            }
        __syncthreads();
    }

    // normalize + softmax over 9-window
    float nc = sqrtf(np[4]);
    float s[9], m = -1e30f;
#pragma unroll
    for (int k = 0; k < 9; k++) {
        s[k] = sim[k] / (nc * sqrtf(np[k]) + 1e-7f);
        m = fmaxf(m, s[k]);
    }
    float sum = 0.f;
#pragma unroll
    for (int k = 0; k < 9; k++) { s[k] = expf(s[k] - m); sum += s[k]; }
    float rinv = 1.f / sum;
#pragma unroll
    for (int k = 0; k < 9; k++) s[k] *= rinv;

    // pass 2: weighted aggregation of original x
    for (int c = 0; c < C_; c++) {
        const float* src = x + ((size_t)b * C_ + c) * HW;
        for (int idx = tid; idx < 660; idx += 512) {
            int r  = idx / 66, cc = idx % 66;
            int gh = h0 - 1 + r, gw = cc - 1;
            float v = 0.f;
            if ((unsigned)gh < (unsigned)H_ && (unsigned)gw < (unsigned)W_)
                v = src[gh * W_ + gw];
            tile[r][cc] = v;
        }
        __syncthreads();
        float a = 0.f;
#pragma unroll
        for (int i = 0; i < 3; i++)
#pragma unroll
            for (int j = 0; j < 3; j++)
                a += s[i * 3 + j] * tile[lr + i][w + j];
        agg[((size_t)b * C_ + c) * HW + (size_t)(h0 + lr) * W_ + w] = a;
        __syncthreads();
    }
}

// ------------------------- global average pooling ---------------------------
__global__ void pool_kernel(const float* __restrict__ x, const float* __restrict__ enh,
                            float* __restrict__ pooled)
{
    const int b  = blockIdx.y;
    const int cc = blockIdx.x;  // 0..511
    const float* src = (cc < C_) ? (x   + ((size_t)b * C_ + cc)       * HW)
                                 : (enh + ((size_t)b * C_ + cc - C_)  * HW);
    float s = 0.f;
    for (int i = threadIdx.x; i < HW; i += 128) s += src[i];
#pragma unroll
    for (int off = 16; off > 0; off >>= 1)
        s += __shfl_down_sync(0xffffffffu, s, off);
    __shared__ float red[4];
    if ((threadIdx.x & 31) == 0) red[threadIdx.x >> 5] = s;
    __syncthreads();
    if (threadIdx.x == 0)
        pooled[b * (2 * C_) + cc] = (red[0] + red[1] + red[2] + red[3]) * (1.f / (float)HW);
}

// ------------------------- SE gating -----------------------------------------
__global__ __launch_bounds__(256)
void gate_kernel(const float* __restrict__ pooled,
                 const float* __restrict__ wg1, const float* __restrict__ bg1,
                 const float* __restrict__ wg2, const float* __restrict__ bg2,
                 float* __restrict__ wts)
{
    const int b = blockIdx.x;
    __shared__ float sp[512];
    __shared__ float sh[64];
    const int tid = threadIdx.x;
    for (int i = tid; i < 512; i += 256) sp[i] = pooled[b * 512 + i];
    __syncthreads();
    if (tid < 64) {
        float a = bg1[tid];
        for (int i = 0; i < 512; i++) a += wg1[tid * 512 + i] * sp[i];
        sh[tid] = fmaxf(a, 0.f);
    }
    __syncthreads();
    float a = bg2[tid];
#pragma unroll
    for (int j = 0; j < 64; j++) a += wg2[tid * 64 + j] * sh[j];
    wts[b * C_ + tid] = 1.f / (1.f + expf(-a));
}

// ------------------------- residual output -----------------------------------
__global__ void final_kernel(const float* __restrict__ x, const float* __restrict__ enh,
                             const float* __restrict__ wts, float* __restrict__ out)
{
    size_t i4 = (size_t)blockIdx.x * 256 + threadIdx.x;   // float4 index
    size_t bc = i4 / (HW / 4);                            // b*C + c
    float wv = wts[bc];
    float4 xv = ((const float4*)x)[i4];
    float4 ev = ((const float4*)enh)[i4];
    float4 o;
    o.x = xv.x + wv * ev.x;  o.y = xv.y + wv * ev.y;
    o.z = xv.z + wv * ev.z;  o.w = xv.w + wv * ev.w;
    ((float4*)out)[i4] = o;
}

// ------------------------- launcher ------------------------------------------
extern "C" void kernel_launch(void* const* d_in, const int* in_sizes, int n_in,
                              void* d_out, int out_size)
{
    const float* x        = (const float*)d_in[0];
    const float* w_embed  = (const float*)d_in[1];
    const float* b_embed  = (const float*)d_in[2];
    const float* bn1_g    = (const float*)d_in[3];
    const float* bn1_b    = (const float*)d_in[4];
    const float* bn1_m    = (const float*)d_in[5];
    const float* bn1_v    = (const float*)d_in[6];
    const float* w_enh    = (const float*)d_in[7];
    const float* b_enh    = (const float*)d_in[8];
    const float* bn2_g    = (const float*)d_in[9];
    const float* bn2_b    = (const float*)d_in[10];
    const float* bn2_m    = (const float*)d_in[11];
    const float* bn2_v    = (const float*)d_in[12];
    const float* w_g1     = (const float*)d_in[13];
    const float* b_g1     = (const float*)d_in[14];
    const float* w_g2     = (const float*)d_in[15];
    const float* b_g2     = (const float*)d_in[16];
    float* out = (float*)d_out;

    float *fe, *agg, *enh, *W1, *b1, *W2, *b2, *pooled, *wts;
    cudaGetSymbolAddress((void**)&fe,  g_fe);
    cudaGetSymbolAddress((void**)&agg, g_agg);
    cudaGetSymbolAddress((void**)&enh, g_enh);
    cudaGetSymbolAddress((void**)&W1,  g_W1);
    cudaGetSymbolAddress((void**)&b1,  g_b1);
    cudaGetSymbolAddress((void**)&W2,  g_W2);
    cudaGetSymbolAddress((void**)&b2,  g_b2);
    cudaGetSymbolAddress((void**)&pooled, g_pooled);
    cudaGetSymbolAddress((void**)&wts, g_wts);

    // 1) fold BN into conv weights
    fold_bn_kernel<<<C_, 256>>>(w_embed, b_embed, bn1_g, bn1_b, bn1_m, bn1_v, W1, b1, C_);
    fold_bn_kernel<<<C_, 256>>>(w_enh,   b_enh,   bn2_g, bn2_b, bn2_m, bn2_v, W2, b2, 2 * C_);

    // 2) fe = relu(bn1(W_embed @ x))
    dim3 ggrid(HW / 128, C_ / 128, B_);
    gemm_bias_relu_kernel<<<ggrid, 256>>>(W1, x, nullptr, b1, fe, C_);

    // 3) similarity + softmax + aggregation
    dim3 sgrid(H_ / 8, B_);
    simagg_kernel<<<sgrid, 512>>>(fe, x, agg);

    // 4) enhanced = relu(bn2(W_enh @ [x; agg]))
    gemm_bias_relu_kernel<<<ggrid, 256>>>(W2, x, agg, b2, enh, 2 * C_);

    // 5) pooled mean of [x; enhanced]
    dim3 pgrid(2 * C_, B_);
    pool_kernel<<<pgrid, 128>>>(x, enh, pooled);

    // 6) SE gating
    gate_kernel<<<B_, 256>>>(pooled, w_g1, b_g1, w_g2, b_g2, wts);

    // 7) out = x + weights * enhanced
    final_kernel<<<(B_ * C_ * HW / 4) / 256, 256>>>(x, enh, wts, out);
}

// round 2
// speedup vs baseline: 1.8320x; 1.8320x over previous
#include <cuda_runtime.h>
#include <math.h>

#define B_  8
#define C_  256
#define H_  64
#define W_  64
#define HW  (H_*W_)
#define PLANE ((size_t)C_*HW)
#define NCHUNK 8
#define CHUNK  32            // channels per chunk (C_/NCHUNK)
#define TILE_H 8             // rows per spatial tile (full 64-wide rows)
#define HALO_N 660           // (TILE_H+2)*(W_+2) = 10*66

// ------------------------- scratch (static device memory) -------------------
__device__ float g_fe  [B_*C_*HW];
__device__ float g_agg [B_*C_*HW];
__device__ float g_enh [B_*C_*HW];
__device__ float g_W1  [C_*C_];
__device__ float g_b1  [C_];
__device__ float g_W2  [C_*2*C_];
__device__ float g_b2  [C_];
__device__ float g_pooled[B_*2*C_];
__device__ float g_gate[B_*C_];
__device__ float g_part[NCHUNK*B_*10*HW];   // per-chunk partial: 9 dots + 1 norm
__device__ float g_normp[B_*HW];            // summed squared-norm plane
__device__ float g_wts9[9*B_*HW];           // softmax weights, plane-major

// ------------------------- BN folding ---------------------------------------
__global__ void fold_bn_kernel(const float* __restrict__ W, const float* __restrict__ bconv,
                               const float* __restrict__ gamma, const float* __restrict__ beta,
                               const float* __restrict__ mean, const float* __restrict__ var,
                               float* __restrict__ Wo, float* __restrict__ bo, int Kin)
{
    int o = blockIdx.x;
    float inv = gamma[o] / sqrtf(var[o] + 1e-5f);
    for (int i = threadIdx.x; i < Kin; i += blockDim.x)
        Wo[o * Kin + i] = W[o * Kin + i] * inv;
    if (threadIdx.x == 0)
        bo[o] = bconv[o] * inv + beta[o] - mean[o] * inv;
}

// ------------------------- SGEMM: out[b] = relu(A @ X[b] + bias) -------------
__global__ __launch_bounds__(256)
void gemm_bias_relu_kernel(const float* __restrict__ A,
                           const float* __restrict__ X0,
                           const float* __restrict__ X1,
                           const float* __restrict__ bias,
                           float* __restrict__ out, int K)
{
    __shared__ float As[16][128];
    __shared__ float Bs[16][128];

    const int b   = blockIdx.z;
    const int p0  = blockIdx.x * 128;
    const int m0  = blockIdx.y * 128;
    const int tid = threadIdx.x;
    const int tx  = tid & 15;
    const int ty  = tid >> 4;

    float acc[8][8];
#pragma unroll
    for (int i = 0; i < 8; i++)
#pragma unroll
        for (int j = 0; j < 8; j++) acc[i][j] = 0.f;

    const float* xb0 = X0 + (size_t)b * PLANE;
    const float* xb1 = X1 ? (X1 + (size_t)b * PLANE) : nullptr;

    for (int k0 = 0; k0 < K; k0 += 16) {
#pragma unroll
        for (int l = 0; l < 2; l++) {
            int idx = tid + l * 256;
            int r   = idx >> 2;
            int c4  = (idx & 3) * 4;
            float4 v = *(const float4*)(A + (size_t)(m0 + r) * K + k0 + c4);
            As[c4 + 0][r] = v.x; As[c4 + 1][r] = v.y;
            As[c4 + 2][r] = v.z; As[c4 + 3][r] = v.w;
        }
#pragma unroll
        for (int l = 0; l < 2; l++) {
            int idx = tid + l * 256;
            int r   = idx >> 5;
            int c   = (idx & 31) * 4;
            int ci  = k0 + r;
            const float* src = (ci < C_) ? (xb0 + (size_t)ci * HW)
                                         : (xb1 + (size_t)(ci - C_) * HW);
            *(float4*)&Bs[r][c] = *(const float4*)(src + p0 + c);
        }
        __syncthreads();

#pragma unroll
        for (int kk = 0; kk < 16; kk++) {
            float af[8], bf[8];
#pragma unroll
            for (int i = 0; i < 8; i++) af[i] = As[kk][ty * 8 + i];
#pragma unroll
            for (int j = 0; j < 8; j++) bf[j] = Bs[kk][tx * 8 + j];
#pragma unroll
            for (int i = 0; i < 8; i++)
#pragma unroll
                for (int j = 0; j < 8; j++) acc[i][j] += af[i] * bf[j];
        }
        __syncthreads();
    }

#pragma unroll
    for (int i = 0; i < 8; i++) {
        int row = m0 + ty * 8 + i;
        float bs = bias[row];
        float* dst = out + (size_t)b * PLANE + (size_t)row * HW + p0 + tx * 8;
#pragma unroll
        for (int j = 0; j < 8; j += 4) {
            float4 v;
            v.x = fmaxf(acc[i][j + 0] + bs, 0.f);
            v.y = fmaxf(acc[i][j + 1] + bs, 0.f);
            v.z = fmaxf(acc[i][j + 2] + bs, 0.f);
            v.w = fmaxf(acc[i][j + 3] + bs, 0.f);
            *(float4*)(dst + j) = v;
        }
    }
}

// ---------------- sim partials: per-chunk 9 dots + own norm ------------------
// grid (8 row-tiles, B, NCHUNK), 128 threads, 4 pixels per thread.
__global__ __launch_bounds__(128)
void sim_part_kernel(const float* __restrict__ fe, float* __restrict__ part)
{
    const int h0 = blockIdx.x * TILE_H;
    const int b  = blockIdx.y;
    const int ch = blockIdx.z;
    const int c0 = ch * CHUNK;
    const int tid = threadIdx.x;
    const int lr = tid >> 4;            // 0..7
    const int base = (tid & 15) * 4;    // 0..60, 4 px each

    __shared__ float tile[HALO_N];      // 10 x 66

    float sacc[9][4];
    float nrm[4];
#pragma unroll
    for (int k = 0; k < 9; k++)
#pragma unroll
        for (int t = 0; t < 4; t++) sacc[k][t] = 0.f;
#pragma unroll
    for (int t = 0; t < 4; t++) nrm[t] = 0.f;

    const float* src = fe + ((size_t)b * C_ + c0) * HW;
    float pre[6];
    // preload channel 0 halo
#pragma unroll
    for (int l = 0; l < 6; l++) {
        int idx = tid + l * 128;
        float v = 0.f;
        if (idx < HALO_N) {
            int r = idx / 66, cc = idx - r * 66;
            int gh = h0 - 1 + r, gw = cc - 1;
            if ((unsigned)gh < (unsigned)H_ && (unsigned)gw < (unsigned)W_)
                v = src[gh * W_ + gw];
        }
        pre[l] = v;
    }

    for (int c = 0; c < CHUNK; c++) {
        // commit prefetched halo to smem
#pragma unroll
        for (int l = 0; l < 6; l++) {
            int idx = tid + l * 128;
            if (idx < HALO_N) tile[idx] = pre[l];
        }
        __syncthreads();

        // prefetch next channel while computing this one
        if (c + 1 < CHUNK) {
            const float* nsrc = src + (size_t)(c + 1) * HW;
#pragma unroll
            for (int l = 0; l < 6; l++) {
                int idx = tid + l * 128;
                float v = 0.f;
                if (idx < HALO_N) {
                    int r = idx / 66, cc = idx - r * 66;
                    int gh = h0 - 1 + r, gw = cc - 1;
                    if ((unsigned)gh < (unsigned)H_ && (unsigned)gw < (unsigned)W_)
                        v = nsrc[gh * W_ + gw];
                }
                pre[l] = v;
            }
        }

        float v0[6], v1[6], v2[6];
#pragma unroll
        for (int m = 0; m < 6; m++) {
            v0[m] = tile[(lr + 0) * 66 + base + m];
            v1[m] = tile[(lr + 1) * 66 + base + m];
            v2[m] = tile[(lr + 2) * 66 + base + m];
        }
#pragma unroll
        for (int t = 0; t < 4; t++) {
            float cv = v1[t + 1];
            nrm[t] += cv * cv;
#pragma unroll
            for (int j = 0; j < 3; j++) {
                sacc[0 + j][t] += cv * v0[t + j];
                sacc[3 + j][t] += cv * v1[t + j];
                sacc[6 + j][t] += cv * v2[t + j];
            }
        }
        __syncthreads();
    }

    // write partials: part[ch][b][k][hw]
    const size_t pbase = ((size_t)(ch * B_ + b)) * 10 * HW + (size_t)(h0 + lr) * W_ + base;
#pragma unroll
    for (int k = 0; k < 9; k++) {
        float4 v = make_float4(sacc[k][0], sacc[k][1], sacc[k][2], sacc[k][3]);
        *(float4*)(part + pbase + (size_t)k * HW) = v;
    }
    *(float4*)(part + pbase + (size_t)9 * HW) =
        make_float4(nrm[0], nrm[1], nrm[2], nrm[3]);
}

// ---------------- sum chunk norm planes --------------------------------------
__global__ void norm_sum_kernel(const float* __restrict__ part, float* __restrict__ normp)
{
    int p = blockIdx.x * 256 + threadIdx.x;     // b*HW + hw
    int b = p >> 12, hw = p & (HW - 1);
    float s = 0.f;
#pragma unroll
    for (int ch = 0; ch < NCHUNK; ch++)
        s += part[((size_t)(ch * B_ + b) * 10 + 9) * HW + hw];
    normp[p] = s;
}

// ---------------- per-pixel cosine + softmax -> 9 weight planes --------------
__global__ void weights_kernel(const float* __restrict__ part,
                               const float* __restrict__ normp,
                               float* __restrict__ wts)
{
    int p  = blockIdx.x * 256 + threadIdx.x;    // 0..32767
    int b  = p >> 12, hw = p & (HW - 1);
    int h  = hw >> 6,  w = hw & 63;

    float sim[9];
#pragma unroll
    for (int k = 0; k < 9; k++) sim[k] = 0.f;
#pragma unroll
    for (int ch = 0; ch < NCHUNK; ch++) {
        const float* pp = part + (size_t)(ch * B_ + b) * 10 * HW + hw;
#pragma unroll
        for (int k = 0; k < 9; k++) sim[k] += pp[(size_t)k * HW];
    }
    float nc = sqrtf(normp[p]);

    float s[9], m = -1e30f;
#pragma unroll
    for (int i = 0; i < 3; i++)
#pragma unroll
        for (int j = 0; j < 3; j++) {
            int nh = h + i - 1, nw = w + j - 1;
            float nb = 0.f;
            if ((unsigned)nh < (unsigned)H_ && (unsigned)nw < (unsigned)W_)
                nb = normp[b * HW + nh * W_ + nw];
            int k = i * 3 + j;
            s[k] = sim[k] / (nc * sqrtf(nb) + 1e-7f);
            m = fmaxf(m, s[k]);
        }
    float sum = 0.f;
#pragma unroll
    for (int k = 0; k < 9; k++) { s[k] = expf(s[k] - m); sum += s[k]; }
    float rinv = 1.f / sum;
#pragma unroll
    for (int k = 0; k < 9; k++)
        wts[(size_t)k * (B_ * HW) + p] = s[k] * rinv;
}

// ---------------- weighted aggregation of x ----------------------------------
// grid (8 row-tiles, B, NCHUNK), 128 threads, 4 px/thread, 32 channels/block.
__global__ __launch_bounds__(128)
void agg_kernel(const float* __restrict__ x, const float* __restrict__ wts,
                float* __restrict__ agg)
{
    const int h0 = blockIdx.x * TILE_H;
    const int b  = blockIdx.y;
    const int c0 = blockIdx.z * CHUNK;
    const int tid = threadIdx.x;
    const int lr = tid >> 4;
    const int base = (tid & 15) * 4;

    __shared__ float tile[HALO_N];

    // load my 4 pixels' 9 weights
    float w9[9][4];
    {
        size_t pidx = (size_t)b * HW + (size_t)(h0 + lr) * W_ + base;
#pragma unroll
        for (int k = 0; k < 9; k++) {
            float4 v = *(const float4*)(wts + (size_t)k * (B_ * HW) + pidx);
            w9[k][0] = v.x; w9[k][1] = v.y; w9[k][2] = v.z; w9[k][3] = v.w;
        }
    }

    const float* src = x + ((size_t)b * C_ + c0) * HW;
    float pre[6];
#pragma unroll
    for (int l = 0; l < 6; l++) {
        int idx = tid + l * 128;
        float v = 0.f;
        if (idx < HALO_N) {
            int r = idx / 66, cc = idx - r * 66;
            int gh = h0 - 1 + r, gw = cc - 1;
            if ((unsigned)gh < (unsigned)H_ && (unsigned)gw < (unsigned)W_)
                v = src[gh * W_ + gw];
        }
        pre[l] = v;
    }

    for (int c = 0; c < CHUNK; c++) {
#pragma unroll
        for (int l = 0; l < 6; l++) {
            int idx = tid + l * 128;
            if (idx < HALO_N) tile[idx] = pre[l];
        }
        __syncthreads();

        if (c + 1 < CHUNK) {
            const float* nsrc = src + (size_t)(c + 1) * HW;
#pragma unroll
            for (int l = 0; l < 6; l++) {
                int idx = tid + l * 128;
                float v = 0.f;
                if (idx < HALO_N) {
                    int r = idx / 66, cc = idx - r * 66;
                    int gh = h0 - 1 + r, gw = cc - 1;
                    if ((unsigned)gh < (unsigned)H_ && (unsigned)gw < (unsigned)W_)
                        v = nsrc[gh * W_ + gw];
                }
                pre[l] = v;
            }
        }

        float v0[6], v1[6], v2[6];
#pragma unroll
        for (int m = 0; m < 6; m++) {
            v0[m] = tile[(lr + 0) * 66 + base + m];
            v1[m] = tile[(lr + 1) * 66 + base + m];
            v2[m] = tile[(lr + 2) * 66 + base + m];
        }
        float a[4];
#pragma unroll
        for (int t = 0; t < 4; t++) {
            float acc = 0.f;
#pragma unroll
            for (int j = 0; j < 3; j++) {
                acc += w9[0 + j][t] * v0[t + j];
                acc += w9[3 + j][t] * v1[t + j];
                acc += w9[6 + j][t] * v2[t + j];
            }
            a[t] = acc;
        }
        float* dst = agg + ((size_t)b * C_ + c0 + c) * HW + (size_t)(h0 + lr) * W_ + base;
        *(float4*)dst = make_float4(a[0], a[1], a[2], a[3]);
        __syncthreads();
    }
}

// ------------------------- global average pooling ---------------------------
__global__ void pool_kernel(const float* __restrict__ x, const float* __restrict__ enh,
                            float* __restrict__ pooled)
{
    const int b  = blockIdx.y;
    const int cc = blockIdx.x;
    const float* src = (cc < C_) ? (x   + ((size_t)b * C_ + cc)      * HW)
                                 : (enh + ((size_t)b * C_ + cc - C_) * HW);
    float s = 0.f;
    for (int i = threadIdx.x; i < HW; i += 128) s += src[i];
#pragma unroll
    for (int off = 16; off > 0; off >>= 1)
        s += __shfl_down_sync(0xffffffffu, s, off);
    __shared__ float red[4];
    if ((threadIdx.x & 31) == 0) red[threadIdx.x >> 5] = s;
    __syncthreads();
    if (threadIdx.x == 0)
        pooled[b * (2 * C_) + cc] = (red[0] + red[1] + red[2] + red[3]) * (1.f / (float)HW);
}

// ------------------------- SE gating -----------------------------------------
__global__ __launch_bounds__(256)
void gate_kernel(const float* __restrict__ pooled,
                 const float* __restrict__ wg1, const float* __restrict__ bg1,
                 const float* __restrict__ wg2, const float* __restrict__ bg2,
                 float* __restrict__ gate)
{
    const int b = blockIdx.x;
    __shared__ float sp[512];
    __shared__ float sh[64];
    const int tid = threadIdx.x;
    for (int i = tid; i < 512; i += 256) sp[i] = pooled[b * 512 + i];
    __syncthreads();
    if (tid < 64) {
        float a = bg1[tid];
        for (int i = 0; i < 512; i++) a += wg1[tid * 512 + i] * sp[i];
        sh[tid] = fmaxf(a, 0.f);
    }
    __syncthreads();
    float a = bg2[tid];
#pragma unroll
    for (int j = 0; j < 64; j++) a += wg2[tid * 64 + j] * sh[j];
    gate[b * C_ + tid] = 1.f / (1.f + expf(-a));
}

// ------------------------- residual output -----------------------------------
__global__ void final_kernel(const float* __restrict__ x, const float* __restrict__ enh,
                             const float* __restrict__ gate, float* __restrict__ out)
{
    size_t i4 = (size_t)blockIdx.x * 256 + threadIdx.x;
    size_t bc = i4 / (HW / 4);
    float wv = gate[bc];
    float4 xv = ((const float4*)x)[i4];
    float4 ev = ((const float4*)enh)[i4];
    float4 o;
    o.x = xv.x + wv * ev.x;  o.y = xv.y + wv * ev.y;
    o.z = xv.z + wv * ev.z;  o.w = xv.w + wv * ev.w;
    ((float4*)out)[i4] = o;
}

// ------------------------- launcher ------------------------------------------
extern "C" void kernel_launch(void* const* d_in, const int* in_sizes, int n_in,
                              void* d_out, int out_size)
{
    const float* x        = (const float*)d_in[0];
    const float* w_embed  = (const float*)d_in[1];
    const float* b_embed  = (const float*)d_in[2];
    const float* bn1_g    = (const float*)d_in[3];
    const float* bn1_b    = (const float*)d_in[4];
    const float* bn1_m    = (const float*)d_in[5];
    const float* bn1_v    = (const float*)d_in[6];
    const float* w_enh    = (const float*)d_in[7];
    const float* b_enh    = (const float*)d_in[8];
    const float* bn2_g    = (const float*)d_in[9];
    const float* bn2_b    = (const float*)d_in[10];
    const float* bn2_m    = (const float*)d_in[11];
    const float* bn2_v    = (const float*)d_in[12];
    const float* w_g1     = (const float*)d_in[13];
    const float* b_g1     = (const float*)d_in[14];
    const float* w_g2     = (const float*)d_in[15];
    const float* b_g2     = (const float*)d_in[16];
    float* out = (float*)d_out;

    float *fe, *agg, *enh, *W1, *b1, *W2, *b2, *pooled, *gate, *part, *normp, *wts;
    cudaGetSymbolAddress((void**)&fe,   g_fe);
    cudaGetSymbolAddress((void**)&agg,  g_agg);
    cudaGetSymbolAddress((void**)&enh,  g_enh);
    cudaGetSymbolAddress((void**)&W1,   g_W1);
    cudaGetSymbolAddress((void**)&b1,   g_b1);
    cudaGetSymbolAddress((void**)&W2,   g_W2);
    cudaGetSymbolAddress((void**)&b2,   g_b2);
    cudaGetSymbolAddress((void**)&pooled, g_pooled);
    cudaGetSymbolAddress((void**)&gate, g_gate);
    cudaGetSymbolAddress((void**)&part, g_part);
    cudaGetSymbolAddress((void**)&normp, g_normp);
    cudaGetSymbolAddress((void**)&wts,  g_wts9);

    // 1) fold BN into conv weights
    fold_bn_kernel<<<C_, 256>>>(w_embed, b_embed, bn1_g, bn1_b, bn1_m, bn1_v, W1, b1, C_);
    fold_bn_kernel<<<C_, 256>>>(w_enh,   b_enh,   bn2_g, bn2_b, bn2_m, bn2_v, W2, b2, 2 * C_);

    // 2) fe = relu(bn1(W_embed @ x))
    dim3 ggrid(HW / 128, C_ / 128, B_);
    gemm_bias_relu_kernel<<<ggrid, 256>>>(W1, x, nullptr, b1, fe, C_);

    // 3) similarity partials -> norms -> softmax weights -> aggregation
    dim3 sgrid(H_ / TILE_H, B_, NCHUNK);
    sim_part_kernel<<<sgrid, 128>>>(fe, part);
    norm_sum_kernel<<<(B_ * HW) / 256, 256>>>(part, normp);
    weights_kernel<<<(B_ * HW) / 256, 256>>>(part, normp, wts);
    agg_kernel<<<sgrid, 128>>>(x, wts, agg);

    // 4) enhanced = relu(bn2(W_enh @ [x; agg]))
    gemm_bias_relu_kernel<<<ggrid, 256>>>(W2, x, agg, b2, enh, 2 * C_);

    // 5) pooled mean of [x; enhanced]
    dim3 pgrid(2 * C_, B_);
    pool_kernel<<<pgrid, 128>>>(x, enh, pooled);

    // 6) SE gating
    gate_kernel<<<B_, 256>>>(pooled, w_g1, b_g1, w_g2, b_g2, gate);

    // 7) out = x + weights * enhanced
    final_kernel<<<(B_ * C_ * HW / 4) / 256, 256>>>(x, enh, gate, out);
}

// round 5
// speedup vs baseline: 3.2611x; 1.7801x over previous
#include <cuda_runtime.h>
#include <cuda_bf16.h>
#include <math.h>
#include <stdint.h>

#define B_  8
#define C_  256
#define H_  64
#define W_  64
#define HW  (H_*W_)
#define PLANE ((size_t)C_*HW)
#define NCHUNK 8
#define CHUNK  32
#define TILE_H 8
#define HALO_N 660
#define ASTRIDE 40      // bf16 elems per A smem row (32 + pad, conflict-free ldmatrix)
#define BSTRIDE 136     // bf16 elems per B smem row (128 + pad)

// ------------------------- scratch (static device memory) -------------------
__device__ float g_fe  [B_*C_*HW];
__device__ float g_agg [B_*C_*HW];
__device__ float g_enh [B_*C_*HW];
__device__ float g_b1  [C_];
__device__ float g_b2  [C_];
__device__ float g_pooled[B_*2*C_];
__device__ float g_gate[B_*C_];
__device__ float g_part[NCHUNK*B_*10*HW];
__device__ float g_normp[B_*HW];
__device__ float g_wts9[9*B_*HW];
__device__ __nv_bfloat16 g_W1hi[C_*C_];
__device__ __nv_bfloat16 g_W1lo[C_*C_];
__device__ __nv_bfloat16 g_W2hi[C_*2*C_];
__device__ __nv_bfloat16 g_W2lo[C_*2*C_];

// ------------------------- PTX helpers (baseline ISA only) ------------------
__device__ __forceinline__ uint32_t smem_u32(const void* p) {
    uint32_t a;
    asm("{ .reg .u64 t; cvta.to.shared.u64 t, %1; cvt.u32.u64 %0, t; }" : "=r"(a) : "l"(p));
    return a;
}
#define LDSM4(r0,r1,r2,r3,addr) \
    asm volatile("ldmatrix.sync.aligned.m8n8.x4.shared.b16 {%0,%1,%2,%3}, [%4];" \
                 : "=r"(r0),"=r"(r1),"=r"(r2),"=r"(r3) : "r"(addr))
#define LDSM4T(r0,r1,r2,r3,addr) \
    asm volatile("ldmatrix.sync.aligned.m8n8.x4.trans.shared.b16 {%0,%1,%2,%3}, [%4];" \
                 : "=r"(r0),"=r"(r1),"=r"(r2),"=r"(r3) : "r"(addr))
#define MMA_BF16(d,a,b) \
    asm volatile("mma.sync.aligned.m16n8k16.row.col.f32.bf16.bf16.f32 " \
                 "{%0,%1,%2,%3},{%4,%5,%6,%7},{%8,%9},{%0,%1,%2,%3};" \
                 : "+f"((d)[0]),"+f"((d)[1]),"+f"((d)[2]),"+f"((d)[3]) \
                 : "r"((a)[0]),"r"((a)[1]),"r"((a)[2]),"r"((a)[3]), \
                   "r"((b)[0]),"r"((b)[1]))

__device__ __forceinline__ uint32_t pack_bf16x2(__nv_bfloat16 a, __nv_bfloat16 b) {
    return (uint32_t)__bfloat16_as_ushort(a) | ((uint32_t)__bfloat16_as_ushort(b) << 16);
}

// ------------------------- BN fold + bf16 split ------------------------------
__global__ void fold_split_kernel(const float* __restrict__ W, const float* __restrict__ bconv,
                                  const float* __restrict__ gamma, const float* __restrict__ beta,
                                  const float* __restrict__ mean, const float* __restrict__ var,
                                  __nv_bfloat16* __restrict__ Whi, __nv_bfloat16* __restrict__ Wlo,
                                  float* __restrict__ bo, int Kin)
{
    int o = blockIdx.x;
    float inv = gamma[o] / sqrtf(var[o] + 1e-5f);
    for (int i = threadIdx.x; i < Kin; i += blockDim.x) {
        float w = W[o * Kin + i] * inv;
        __nv_bfloat16 hb = __float2bfloat16(w);
        Whi[o * Kin + i] = hb;
        Wlo[o * Kin + i] = __float2bfloat16(w - __bfloat162float(hb));
    }
    if (threadIdx.x == 0)
        bo[o] = bconv[o] * inv + beta[o] - mean[o] * inv;
}

// ---------------- HMMA bf16x3 GEMM: out = relu(W @ X + bias) -----------------
// A = W [M=256 rows][K] bf16 hi/lo (row-major, k contiguous).
// B = activations, natural layout [K channels][N pixels] f32; rows 0..255 from
// X0, 256..K-1 from X1; f32->bf16 hi/lo split during smem staging.
// CTA tile 128x128, BK=32, 8 warps (4m x 2n), warp tile 32x64 (2x8 m16n8k16).
__global__ __launch_bounds__(256)
void gemm_mma_kernel(const __nv_bfloat16* __restrict__ Whi,
                     const __nv_bfloat16* __restrict__ Wlo,
                     const float* __restrict__ X0,
                     const float* __restrict__ X1,
                     const float* __restrict__ bias,
                     float* __restrict__ out, int Kw)
{
    __shared__ __nv_bfloat16 sAh[128*ASTRIDE];
    __shared__ __nv_bfloat16 sAl[128*ASTRIDE];
    __shared__ __nv_bfloat16 sBh[32*BSTRIDE];
    __shared__ __nv_bfloat16 sBl[32*BSTRIDE];

    const int tid = threadIdx.x, lane = tid & 31, wid = tid >> 5;
    const int mw = wid & 3, nw = wid >> 2;
    const int p0 = blockIdx.x * 128, m0 = blockIdx.y * 128, b = blockIdx.z;

    float acc[2][8][4];
#pragma unroll
    for (int i = 0; i < 2; i++)
#pragma unroll
        for (int j = 0; j < 8; j++)
#pragma unroll
            for (int q = 0; q < 4; q++) acc[i][j][q] = 0.f;

    const uint32_t aAh = smem_u32(sAh), aAl = smem_u32(sAl);
    const uint32_t aBh = smem_u32(sBh), aBl = smem_u32(sBl);

    // per-lane ldmatrix byte offsets
    // A (16x16, row-major): lanes 0-15 -> rows, lanes 16-31 -> rows, col +8
    const uint32_t aoff = (uint32_t)(((mw * 32 + (lane & 15)) * ASTRIDE
                                      + (lane >> 4) * 8) * 2);
    // B (row-major [k][n], trans): lanes 0-7 k0-7, 8-15 k8-15, 16-23 k0-7 n+8, 24-31 k8-15 n+8
    const uint32_t boff = (uint32_t)(((((lane & 7) | (((lane >> 3) & 1) << 3)) * BSTRIDE)
                                      + nw * 64 + (lane >> 4) * 8) * 2);

    for (int k0 = 0; k0 < Kw; k0 += 32) {
        // ---- stage A: 128 rows x 32 k, hi+lo (2 uint4 per thread per split)
#pragma unroll
        for (int i = 0; i < 2; i++) {
            int idx = tid + i * 256;         // 0..511
            int r = idx >> 2, c = (idx & 3) * 8;
            size_t go = (size_t)(m0 + r) * Kw + k0 + c;
            *(uint4*)&sAh[r * ASTRIDE + c] = *(const uint4*)(Whi + go);
            *(uint4*)&sAl[r * ASTRIDE + c] = *(const uint4*)(Wlo + go);
        }
        // ---- stage B: 32 k-rows x 128 px, f32 -> bf16 hi/lo split
#pragma unroll
        for (int j = 0; j < 4; j++) {
            int idx = tid + j * 256;         // 0..1023
            int k = idx >> 5, n4 = (idx & 31) * 4;
            int kg = k0 + k;
            const float* src = (kg < C_) ? X0 + ((size_t)b * C_ + kg) * HW
                                         : X1 + ((size_t)b * C_ + kg - C_) * HW;
            float4 v = *(const float4*)(src + p0 + n4);
            __nv_bfloat16 hx = __float2bfloat16(v.x);
            __nv_bfloat16 hy = __float2bfloat16(v.y);
            __nv_bfloat16 hz = __float2bfloat16(v.z);
            __nv_bfloat16 hw = __float2bfloat16(v.w);
            uint2 hv = make_uint2(pack_bf16x2(hx, hy), pack_bf16x2(hz, hw));
            uint2 lv = make_uint2(
                pack_bf16x2(__float2bfloat16(v.x - __bfloat162float(hx)),
                            __float2bfloat16(v.y - __bfloat162float(hy))),
                pack_bf16x2(__float2bfloat16(v.z - __bfloat162float(hz)),
                            __float2bfloat16(v.w - __bfloat162float(hw))));
            *(uint2*)&sBh[k * BSTRIDE + n4] = hv;
            *(uint2*)&sBl[k * BSTRIDE + n4] = lv;
        }
        __syncthreads();

#pragma unroll
        for (int ks = 0; ks < 2; ks++) {
            uint32_t ah[2][4], al[2][4];
#pragma unroll
            for (int mf = 0; mf < 2; mf++) {
                uint32_t o = aoff + (uint32_t)(mf * 16 * ASTRIDE * 2 + ks * 32);
                LDSM4(ah[mf][0], ah[mf][1], ah[mf][2], ah[mf][3], aAh + o);
                LDSM4(al[mf][0], al[mf][1], al[mf][2], al[mf][3], aAl + o);
            }
            uint32_t bf[8][2];
            // hi B: acc += Ahi*Bhi + Alo*Bhi
#pragma unroll
            for (int np = 0; np < 4; np++) {
                uint32_t o = boff + (uint32_t)(ks * 16 * BSTRIDE * 2 + np * 32);
                LDSM4T(bf[2*np][0], bf[2*np][1], bf[2*np+1][0], bf[2*np+1][1], aBh + o);
            }
#pragma unroll
            for (int mf = 0; mf < 2; mf++)
#pragma unroll
                for (int nf = 0; nf < 8; nf++) {
                    MMA_BF16(acc[mf][nf], ah[mf], bf[nf]);
                    MMA_BF16(acc[mf][nf], al[mf], bf[nf]);
                }
            // lo B: acc += Ahi*Blo
#pragma unroll
            for (int np = 0; np < 4; np++) {
                uint32_t o = boff + (uint32_t)(ks * 16 * BSTRIDE * 2 + np * 32);
                LDSM4T(bf[2*np][0], bf[2*np][1], bf[2*np+1][0], bf[2*np+1][1], aBl + o);
            }
#pragma unroll
            for (int mf = 0; mf < 2; mf++)
#pragma unroll
                for (int nf = 0; nf < 8; nf++)
                    MMA_BF16(acc[mf][nf], ah[mf], bf[nf]);
        }
        __syncthreads();
    }

    // ---- epilogue: bias + relu, direct f32 stores
    const int rr = lane >> 2, cc2 = (lane & 3) * 2;
#pragma unroll
    for (int mf = 0; mf < 2; mf++) {
        int row = m0 + mw * 32 + mf * 16 + rr;
        float bs0 = bias[row], bs1 = bias[row + 8];
        float* d0 = out + ((size_t)b * C_ + row) * HW + p0 + nw * 64 + cc2;
        float* d1 = d0 + 8 * HW;
#pragma unroll
        for (int nf = 0; nf < 8; nf++) {
            float2 v0, v1;
            v0.x = fmaxf(acc[mf][nf][0] + bs0, 0.f);
            v0.y = fmaxf(acc[mf][nf][1] + bs0, 0.f);
            v1.x = fmaxf(acc[mf][nf][2] + bs1, 0.f);
            v1.y = fmaxf(acc[mf][nf][3] + bs1, 0.f);
            *(float2*)(d0 + nf * 8) = v0;
            *(float2*)(d1 + nf * 8) = v1;
        }
    }
}

// ---------------- sim partials (unchanged, proven) ----------------------------
__global__ __launch_bounds__(128)
void sim_part_kernel(const float* __restrict__ fe, float* __restrict__ part)
{
    const int h0 = blockIdx.x * TILE_H;
    const int b  = blockIdx.y;
    const int ch = blockIdx.z;
    const int c0 = ch * CHUNK;
    const int tid = threadIdx.x;
    const int lr = tid >> 4;
    const int base = (tid & 15) * 4;

    __shared__ float tile[HALO_N];

    float sacc[9][4];
    float nrm[4];
#pragma unroll
    for (int k = 0; k < 9; k++)
#pragma unroll
        for (int t = 0; t < 4; t++) sacc[k][t] = 0.f;
#pragma unroll
    for (int t = 0; t < 4; t++) nrm[t] = 0.f;

    const float* src = fe + ((size_t)b * C_ + c0) * HW;
    float pre[6];
#pragma unroll
    for (int l = 0; l < 6; l++) {
        int idx = tid + l * 128;
        float v = 0.f;
        if (idx < HALO_N) {
            int r = idx / 66, cc = idx - r * 66;
            int gh = h0 - 1 + r, gw = cc - 1;
            if ((unsigned)gh < (unsigned)H_ && (unsigned)gw < (unsigned)W_)
                v = src[gh * W_ + gw];
        }
        pre[l] = v;
    }

    for (int c = 0; c < CHUNK; c++) {
#pragma unroll
        for (int l = 0; l < 6; l++) {
            int idx = tid + l * 128;
            if (idx < HALO_N) tile[idx] = pre[l];
        }
        __syncthreads();
        if (c + 1 < CHUNK) {
            const float* nsrc = src + (size_t)(c + 1) * HW;
#pragma unroll
            for (int l = 0; l < 6; l++) {
                int idx = tid + l * 128;
                float v = 0.f;
                if (idx < HALO_N) {
                    int r = idx / 66, cc = idx - r * 66;
                    int gh = h0 - 1 + r, gw = cc - 1;
                    if ((unsigned)gh < (unsigned)H_ && (unsigned)gw < (unsigned)W_)
                        v = nsrc[gh * W_ + gw];
                }
                pre[l] = v;
            }
        }
        float v0[6], v1[6], v2[6];
#pragma unroll
        for (int m = 0; m < 6; m++) {
            v0[m] = tile[(lr + 0) * 66 + base + m];
            v1[m] = tile[(lr + 1) * 66 + base + m];
            v2[m] = tile[(lr + 2) * 66 + base + m];
        }
#pragma unroll
        for (int t = 0; t < 4; t++) {
            float cv = v1[t + 1];
            nrm[t] += cv * cv;
#pragma unroll
            for (int j = 0; j < 3; j++) {
                sacc[0 + j][t] += cv * v0[t + j];
                sacc[3 + j][t] += cv * v1[t + j];
                sacc[6 + j][t] += cv * v2[t + j];
            }
        }
        __syncthreads();
    }

    const size_t pbase = ((size_t)(ch * B_ + b)) * 10 * HW + (size_t)(h0 + lr) * W_ + base;
#pragma unroll
    for (int k = 0; k < 9; k++)
        *(float4*)(part + pbase + (size_t)k * HW) =
            make_float4(sacc[k][0], sacc[k][1], sacc[k][2], sacc[k][3]);
    *(float4*)(part + pbase + (size_t)9 * HW) =
        make_float4(nrm[0], nrm[1], nrm[2], nrm[3]);
}

__global__ void norm_sum_kernel(const float* __restrict__ part, float* __restrict__ normp)
{
    int p = blockIdx.x * 256 + threadIdx.x;
    int b = p >> 12, hw = p & (HW - 1);
    float s = 0.f;
#pragma unroll
    for (int ch = 0; ch < NCHUNK; ch++)
        s += part[((size_t)(ch * B_ + b) * 10 + 9) * HW + hw];
    normp[p] = s;
}

__global__ void weights_kernel(const float* __restrict__ part,
                               const float* __restrict__ normp,
                               float* __restrict__ wts)
{
    int p  = blockIdx.x * 256 + threadIdx.x;
    int b  = p >> 12, hw = p & (HW - 1);
    int h  = hw >> 6,  w = hw & 63;

    float sim[9];
#pragma unroll
    for (int k = 0; k < 9; k++) sim[k] = 0.f;
#pragma unroll
    for (int ch = 0; ch < NCHUNK; ch++) {
        const float* pp = part + (size_t)(ch * B_ + b) * 10 * HW + hw;
#pragma unroll
        for (int k = 0; k < 9; k++) sim[k] += pp[(size_t)k * HW];
    }
    float nc = sqrtf(normp[p]);

    float s[9], m = -1e30f;
#pragma unroll
    for (int i = 0; i < 3; i++)
#pragma unroll
        for (int j = 0; j < 3; j++) {
            int nh = h + i - 1, nw = w + j - 1;
            float nb = 0.f;
            if ((unsigned)nh < (unsigned)H_ && (unsigned)nw < (unsigned)W_)
                nb = normp[b * HW + nh * W_ + nw];
            int k = i * 3 + j;
            s[k] = sim[k] / (nc * sqrtf(nb) + 1e-7f);
            m = fmaxf(m, s[k]);
        }
    float sum = 0.f;
#pragma unroll
    for (int k = 0; k < 9; k++) { s[k] = expf(s[k] - m); sum += s[k]; }
    float rinv = 1.f / sum;
#pragma unroll
    for (int k = 0; k < 9; k++)
        wts[(size_t)k * (B_ * HW) + p] = s[k] * rinv;
}

__global__ __launch_bounds__(128)
void agg_kernel(const float* __restrict__ x, const float* __restrict__ wts,
                float* __restrict__ agg)
{
    const int h0 = blockIdx.x * TILE_H;
    const int b  = blockIdx.y;
    const int c0 = blockIdx.z * CHUNK;
    const int tid = threadIdx.x;
    const int lr = tid >> 4;
    const int base = (tid & 15) * 4;

    __shared__ float tile[HALO_N];

    float w9[9][4];
    {
        size_t pidx = (size_t)b * HW + (size_t)(h0 + lr) * W_ + base;
#pragma unroll
        for (int k = 0; k < 9; k++) {
            float4 v = *(const float4*)(wts + (size_t)k * (B_ * HW) + pidx);
            w9[k][0] = v.x; w9[k][1] = v.y; w9[k][2] = v.z; w9[k][3] = v.w;
        }
    }

    const float* src = x + ((size_t)b * C_ + c0) * HW;
    float pre[6];
#pragma unroll
    for (int l = 0; l < 6; l++) {
        int idx = tid + l * 128;
        float v = 0.f;
        if (idx < HALO_N) {
            int r = idx / 66, cc = idx - r * 66;
            int gh = h0 - 1 + r, gw = cc - 1;
            if ((unsigned)gh < (unsigned)H_ && (unsigned)gw < (unsigned)W_)
                v = src[gh * W_ + gw];
        }
        pre[l] = v;
    }

    for (int c = 0; c < CHUNK; c++) {
#pragma unroll
        for (int l = 0; l < 6; l++) {
            int idx = tid + l * 128;
            if (idx < HALO_N) tile[idx] = pre[l];
        }
        __syncthreads();
        if (c + 1 < CHUNK) {
            const float* nsrc = src + (size_t)(c + 1) * HW;
#pragma unroll
            for (int l = 0; l < 6; l++) {
                int idx = tid + l * 128;
                float v = 0.f;
                if (idx < HALO_N) {
                    int r = idx / 66, cc = idx - r * 66;
                    int gh = h0 - 1 + r, gw = cc - 1;
                    if ((unsigned)gh < (unsigned)H_ && (unsigned)gw < (unsigned)W_)
                        v = nsrc[gh * W_ + gw];
                }
                pre[l] = v;
            }
        }
        float v0[6], v1[6], v2[6];
#pragma unroll
        for (int m = 0; m < 6; m++) {
            v0[m] = tile[(lr + 0) * 66 + base + m];
            v1[m] = tile[(lr + 1) * 66 + base + m];
            v2[m] = tile[(lr + 2) * 66 + base + m];
        }
        float a[4];
#pragma unroll
        for (int t = 0; t < 4; t++) {
            float acc = 0.f;
#pragma unroll
            for (int j = 0; j < 3; j++) {
                acc += w9[0 + j][t] * v0[t + j];
                acc += w9[3 + j][t] * v1[t + j];
                acc += w9[6 + j][t] * v2[t + j];
            }
            a[t] = acc;
        }
        float* dst = agg + ((size_t)b * C_ + c0 + c) * HW + (size_t)(h0 + lr) * W_ + base;
        *(float4*)dst = make_float4(a[0], a[1], a[2], a[3]);
        __syncthreads();
    }
}

// ------------------------- pooling / gating / residual ----------------------
__global__ void pool_kernel(const float* __restrict__ x, const float* __restrict__ enh,
                            float* __restrict__ pooled)
{
    const int b  = blockIdx.y;
    const int cc = blockIdx.x;
    const float* src = (cc < C_) ? (x   + ((size_t)b * C_ + cc)      * HW)
                                 : (enh + ((size_t)b * C_ + cc - C_) * HW);
    float s = 0.f;
    for (int i = threadIdx.x; i < HW; i += 128) s += src[i];
#pragma unroll
    for (int off = 16; off > 0; off >>= 1)
        s += __shfl_down_sync(0xffffffffu, s, off);
    __shared__ float red[4];
    if ((threadIdx.x & 31) == 0) red[threadIdx.x >> 5] = s;
    __syncthreads();
    if (threadIdx.x == 0)
        pooled[b * (2 * C_) + cc] = (red[0] + red[1] + red[2] + red[3]) * (1.f / (float)HW);
}

__global__ __launch_bounds__(256)
void gate_kernel(const float* __restrict__ pooled,
                 const float* __restrict__ wg1, const float* __restrict__ bg1,
                 const float* __restrict__ wg2, const float* __restrict__ bg2,
                 float* __restrict__ gate)
{
    const int b = blockIdx.x;
    __shared__ float sp[512];
    __shared__ float sh[64];
    const int tid = threadIdx.x;
    for (int i = tid; i < 512; i += 256) sp[i] = pooled[b * 512 + i];
    __syncthreads();
    if (tid < 64) {
        float a = bg1[tid];
        for (int i = 0; i < 512; i++) a += wg1[tid * 512 + i] * sp[i];
        sh[tid] = fmaxf(a, 0.f);
    }
    __syncthreads();
    float a = bg2[tid];
#pragma unroll
    for (int j = 0; j < 64; j++) a += wg2[tid * 64 + j] * sh[j];
    gate[b * C_ + tid] = 1.f / (1.f + expf(-a));
}

__global__ void final_kernel(const float* __restrict__ x, const float* __restrict__ enh,
                             const float* __restrict__ gate, float* __restrict__ out)
{
    size_t i4 = (size_t)blockIdx.x * 256 + threadIdx.x;
    size_t bc = i4 / (HW / 4);
    float wv = gate[bc];
    float4 xv = ((const float4*)x)[i4];
    float4 ev = ((const float4*)enh)[i4];
    float4 o;
    o.x = xv.x + wv * ev.x;  o.y = xv.y + wv * ev.y;
    o.z = xv.z + wv * ev.z;  o.w = xv.w + wv * ev.w;
    ((float4*)out)[i4] = o;
}

// ------------------------- launcher ------------------------------------------
extern "C" void kernel_launch(void* const* d_in, const int* in_sizes, int n_in,
                              void* d_out, int out_size)
{
    const float* x        = (const float*)d_in[0];
    const float* w_embed  = (const float*)d_in[1];
    const float* b_embed  = (const float*)d_in[2];
    const float* bn1_g    = (const float*)d_in[3];
    const float* bn1_b    = (const float*)d_in[4];
    const float* bn1_m    = (const float*)d_in[5];
    const float* bn1_v    = (const float*)d_in[6];
    const float* w_enh    = (const float*)d_in[7];
    const float* b_enh    = (const float*)d_in[8];
    const float* bn2_g    = (const float*)d_in[9];
    const float* bn2_b    = (const float*)d_in[10];
    const float* bn2_m    = (const float*)d_in[11];
    const float* bn2_v    = (const float*)d_in[12];
    const float* w_g1     = (const float*)d_in[13];
    const float* b_g1     = (const float*)d_in[14];
    const float* w_g2     = (const float*)d_in[15];
    const float* b_g2     = (const float*)d_in[16];
    float* out = (float*)d_out;

    float *fe, *agg, *enh, *b1, *b2, *pooled, *gate, *part, *normp, *wts;
    __nv_bfloat16 *W1hi, *W1lo, *W2hi, *W2lo;
    cudaGetSymbolAddress((void**)&fe,   g_fe);
    cudaGetSymbolAddress((void**)&agg,  g_agg);
    cudaGetSymbolAddress((void**)&enh,  g_enh);
    cudaGetSymbolAddress((void**)&b1,   g_b1);
    cudaGetSymbolAddress((void**)&b2,   g_b2);
    cudaGetSymbolAddress((void**)&pooled, g_pooled);
    cudaGetSymbolAddress((void**)&gate, g_gate);
    cudaGetSymbolAddress((void**)&part, g_part);
    cudaGetSymbolAddress((void**)&normp, g_normp);
    cudaGetSymbolAddress((void**)&wts,  g_wts9);
    cudaGetSymbolAddress((void**)&W1hi, g_W1hi);
    cudaGetSymbolAddress((void**)&W1lo, g_W1lo);
    cudaGetSymbolAddress((void**)&W2hi, g_W2hi);
    cudaGetSymbolAddress((void**)&W2lo, g_W2lo);

    // 1) BN fold + bf16 hi/lo split of weights
    fold_split_kernel<<<C_, 256>>>(w_embed, b_embed, bn1_g, bn1_b, bn1_m, bn1_v, W1hi, W1lo, b1, C_);
    fold_split_kernel<<<C_, 256>>>(w_enh,   b_enh,   bn2_g, bn2_b, bn2_m, bn2_v, W2hi, W2lo, b2, 2 * C_);

    // 2) fe = relu(bn1(W_embed @ x))   [HMMA bf16x3]
    dim3 ggrid(HW / 128, C_ / 128, B_);
    gemm_mma_kernel<<<ggrid, 256>>>(W1hi, W1lo, x, x, b1, fe, C_);

    // 3) similarity -> softmax weights -> aggregation
    dim3 sgrid(H_ / TILE_H, B_, NCHUNK);
    sim_part_kernel<<<sgrid, 128>>>(fe, part);
    norm_sum_kernel<<<(B_ * HW) / 256, 256>>>(part, normp);
    weights_kernel<<<(B_ * HW) / 256, 256>>>(part, normp, wts);
    agg_kernel<<<sgrid, 128>>>(x, wts, agg);

    // 4) enhanced = relu(bn2(W_enh @ [x; agg]))   [HMMA bf16x3]
    gemm_mma_kernel<<<ggrid, 256>>>(W2hi, W2lo, x, agg, b2, enh, 2 * C_);

    // 5) pooled mean of [x; enhanced]
    dim3 pgrid(2 * C_, B_);
    pool_kernel<<<pgrid, 128>>>(x, enh, pooled);

    // 6) SE gating
    gate_kernel<<<B_, 256>>>(pooled, w_g1, b_g1, w_g2, b_g2, gate);

    // 7) out = x + weights * enhanced
    final_kernel<<<(B_ * C_ * HW / 4) / 256, 256>>>(x, enh, gate, out);
}